// round 12
// baseline (speedup 1.0000x reference)
#include <cuda_runtime.h>
#include <stdint.h>

#define NUM_CLASSES 100000
#define EMBED_DIM   512
#define BATCH       16384
#define ONE_MINUS_ALPHA 0.05f

#define ROWS_PER_BLOCK 8           // one warp per row
#define THREADS_RK     256
#define GRID_RK        (NUM_CLASSES / ROWS_PER_BLOCK)   // 12500

// ---- device scratch (static; zero-init; no allocations) ----
// g_head entries are idx+1 (0 = empty) so the loader's static zero-init IS
// the empty state; row_kernel self-cleans touched entries back to 0 so every
// graph replay starts clean without a 400KB reset pass.
__device__ double       g_loss_acc;            // reset by last block
__device__ unsigned int g_done;                // completion counter, reset by last block
__device__ int          g_head[NUM_CLASSES];   // idx+1 encoded, 0 = empty
__device__ int          g_next[BATCH];         // old head value (idx+1 or 0)

// Single-block kernel: detect label dtype (block-wide consensus), then decode
// labels and build per-class linked lists. int64 labels (< 2^31) have all-zero
// odd int32 words; int32 labels have real values there.
__global__ void __launch_bounds__(256)
build_kernel(const void* __restrict__ labels_raw) {
    const int t = threadIdx.x;

    int any = 0;
    const int* lab32 = (const int*)labels_raw;
    for (int i = t; i < BATCH / 2; i += 256)
        if (lab32[2 * i + 1] != 0) any = 1;
    const int is32 = __syncthreads_or(any);

    for (int i = t; i < BATCH; i += 256) {
        int v = is32 ? lab32[i]
                     : (int)((const long long*)labels_raw)[i];
        if (v < 0) v = 0;
        if (v >= NUM_CLASSES) v = NUM_CLASSES - 1;
        g_next[i] = atomicExch(&g_head[v], i + 1);
    }
}

// Fused pass: 256 threads, 8 rows per block, ONE WARP per row.
// Each thread owns FOUR stride-separated float4s (16 of 512 floats) for 4x
// memory-level parallelism; all four load/store groups are fully coalesced.
// Walks the class's sample list (warp-uniform), accumulates sum(c-f) and
// sum((f-c)^2), writes new = c - 0.05*sum(c-f) exactly once, self-cleans the
// list head, and the LAST block finalizes the loss and resets scratch.
__global__ void __launch_bounds__(THREADS_RK)
row_kernel(const float* __restrict__ features,
           const float* __restrict__ center_var,
           float*       __restrict__ out_centers,
           float*       __restrict__ out_loss) {
    const int t    = threadIdx.x;
    const int w    = t >> 5;          // warp = row within block
    const int lane = t & 31;
    const long long row = (long long)blockIdx.x * ROWS_PER_BLOCK + w;

    const float4* c4 = (const float4*)(center_var + row * EMBED_DIM);
    float4 c0 = __ldcs(c4 + lane);
    float4 c1 = __ldcs(c4 + lane + 32);
    float4 c2 = __ldcs(c4 + lane + 64);
    float4 c3 = __ldcs(c4 + lane + 96);

    float4 d0 = make_float4(0.f,0.f,0.f,0.f);
    float4 d1 = make_float4(0.f,0.f,0.f,0.f);
    float4 d2 = make_float4(0.f,0.f,0.f,0.f);
    float4 d3 = make_float4(0.f,0.f,0.f,0.f);
    float sq = 0.f;
    int   n  = 0;

    const int head = g_head[row];
    for (int h = head; h != 0; ) {
        const int s = h - 1;
        h = g_next[s];                 // warp-uniform broadcast load
        const float4* f4 = (const float4*)(features + (long long)s * EMBED_DIM);
        float4 f0 = __ldcs(f4 + lane);
        float4 f1 = __ldcs(f4 + lane + 32);
        float4 f2 = __ldcs(f4 + lane + 64);
        float4 f3 = __ldcs(f4 + lane + 96);
        float e;
        e = c0.x - f0.x; d0.x += e; sq += e*e;
        e = c0.y - f0.y; d0.y += e; sq += e*e;
        e = c0.z - f0.z; d0.z += e; sq += e*e;
        e = c0.w - f0.w; d0.w += e; sq += e*e;
        e = c1.x - f1.x; d1.x += e; sq += e*e;
        e = c1.y - f1.y; d1.y += e; sq += e*e;
        e = c1.z - f1.z; d1.z += e; sq += e*e;
        e = c1.w - f1.w; d1.w += e; sq += e*e;
        e = c2.x - f2.x; d2.x += e; sq += e*e;
        e = c2.y - f2.y; d2.y += e; sq += e*e;
        e = c2.z - f2.z; d2.z += e; sq += e*e;
        e = c2.w - f2.w; d2.w += e; sq += e*e;
        e = c3.x - f3.x; d3.x += e; sq += e*e;
        e = c3.y - f3.y; d3.y += e; sq += e*e;
        e = c3.z - f3.z; d3.z += e; sq += e*e;
        e = c3.w - f3.w; d3.w += e; sq += e*e;
        n++;
    }

    // Self-clean: return this row's list head to the empty state for the
    // next graph replay (only touched rows pay a store).
    if (lane == 0 && head != 0) g_head[row] = 0;

    // Output rows are +1 float misaligned (loss lives at out[0]) -> scalar stores.
    float* o = out_centers + row * EMBED_DIM + lane * 4;
    __stcs(o +   0, c0.x - ONE_MINUS_ALPHA * d0.x);
    __stcs(o +   1, c0.y - ONE_MINUS_ALPHA * d0.y);
    __stcs(o +   2, c0.z - ONE_MINUS_ALPHA * d0.z);
    __stcs(o +   3, c0.w - ONE_MINUS_ALPHA * d0.w);
    __stcs(o + 128, c1.x - ONE_MINUS_ALPHA * d1.x);
    __stcs(o + 129, c1.y - ONE_MINUS_ALPHA * d1.y);
    __stcs(o + 130, c1.z - ONE_MINUS_ALPHA * d1.z);
    __stcs(o + 131, c1.w - ONE_MINUS_ALPHA * d1.w);
    __stcs(o + 256, c2.x - ONE_MINUS_ALPHA * d2.x);
    __stcs(o + 257, c2.y - ONE_MINUS_ALPHA * d2.y);
    __stcs(o + 258, c2.z - ONE_MINUS_ALPHA * d2.z);
    __stcs(o + 259, c2.w - ONE_MINUS_ALPHA * d2.w);
    __stcs(o + 384, c3.x - ONE_MINUS_ALPHA * d3.x);
    __stcs(o + 385, c3.y - ONE_MINUS_ALPHA * d3.y);
    __stcs(o + 386, c3.z - ONE_MINUS_ALPHA * d3.z);
    __stcs(o + 387, c3.w - ONE_MINUS_ALPHA * d3.w);

    // Block loss reduce (8 warps), one atomic per block that had samples.
    #pragma unroll
    for (int off = 16; off > 0; off >>= 1)
        sq += __shfl_down_sync(0xFFFFFFFFu, sq, off);
    __shared__ float ws[THREADS_RK / 32];
    if (lane == 0) ws[w] = sq;
    const int any = __syncthreads_or(n > 0);
    if (t == 0) {
        if (any) {
            float s = 0.f;
            #pragma unroll
            for (int i = 0; i < THREADS_RK / 32; i++) s += ws[i];
            atomicAdd(&g_loss_acc, (double)s);
        }
        // Last-block-done: finalize loss, reset scratch for the next replay.
        __threadfence();
        unsigned int prev = atomicAdd(&g_done, 1u);
        if (prev == (unsigned int)(gridDim.x - 1)) {
            *out_loss = (float)(g_loss_acc / ((double)BATCH * (double)EMBED_DIM));
            g_loss_acc = 0.0;
            g_done = 0u;
        }
    }
}

extern "C" void kernel_launch(void* const* d_in, const int* in_sizes, int n_in,
                              void* d_out, int out_size) {
    const float* features   = nullptr;
    const void*  labels_raw = nullptr;
    const float* center_var = nullptr;
    for (int i = 0; i < n_in; i++) {
        if (in_sizes[i] == BATCH)                        labels_raw = d_in[i];
        else if (in_sizes[i] == BATCH * EMBED_DIM)       features   = (const float*)d_in[i];
        else if (in_sizes[i] == NUM_CLASSES * EMBED_DIM) center_var = (const float*)d_in[i];
    }
    if (!features)   features   = (const float*)d_in[0];
    if (!labels_raw) labels_raw = d_in[1];
    if (!center_var) center_var = (const float*)d_in[2];

    float* out = (float*)d_out;
    long long centers_off = (long long)out_size - (long long)NUM_CLASSES * EMBED_DIM;
    if (centers_off < 0) centers_off = 0;
    float* out_loss    = out;
    float* out_centers = out + centers_off;

    build_kernel<<<1, 256>>>(labels_raw);
    row_kernel<<<GRID_RK, THREADS_RK>>>(features, center_var, out_centers, out_loss);
}

// round 13
// speedup vs baseline: 1.2755x; 1.2755x over previous
#include <cuda_runtime.h>
#include <stdint.h>

#define NUM_CLASSES 100000
#define EMBED_DIM   512
#define BATCH       16384
#define ONE_MINUS_ALPHA 0.05f

#define ROWS_PER_BLOCK 4           // 64 threads per row (measured-best shape)
#define THREADS_RK     256
#define GRID_RK        (NUM_CLASSES / ROWS_PER_BLOCK)   // 25000

// ---- device scratch (static; zero-init; no allocations) ----
// g_head entries are idx+1 (0 = empty): static zero-init IS the empty state,
// and row_kernel self-cleans touched entries so every graph replay starts clean.
__device__ double       g_loss_acc;            // reset by last row block
__device__ unsigned int g_done;                // completion counter, reset by last block
__device__ int          g_head[NUM_CLASSES];   // idx+1 encoded, 0 = empty
__device__ int          g_next[BATCH];         // old head value (idx+1 or 0)

// Multi-block build: every block independently detects the label dtype by
// scanning the odd int32 words (int64 labels < 2^31 -> all zero; int32 labels
// -> real values there). The 64KB label buffer is L2-resident, so the
// redundant scans are nearly free. Then each block links its slice of samples.
__global__ void __launch_bounds__(256)
build_kernel(const void* __restrict__ labels_raw) {
    const int t   = threadIdx.x;
    const int gid = blockIdx.x * blockDim.x + t;
    const int gs  = gridDim.x * blockDim.x;

    const int* lab32 = (const int*)labels_raw;
    int any = 0;
    for (int i = t; i < BATCH / 2; i += 256)      // per-block full scan (L2 hits)
        if (lab32[2 * i + 1] != 0) any = 1;
    const int is32 = __syncthreads_or(any);

    for (int i = gid; i < BATCH; i += gs) {
        int v = is32 ? lab32[i]
                     : (int)((const long long*)labels_raw)[i];
        if (v < 0) v = 0;
        if (v >= NUM_CLASSES) v = NUM_CLASSES - 1;
        g_next[i] = atomicExch(&g_head[v], i + 1);
    }
}

// Fused pass: 256 threads, 4 rows per block, 64 threads per row.
// Each thread owns TWO stride-separated float4s (8 of 512 floats) — the
// measured-best ILP/occupancy balance. Walks the class's sample list,
// accumulates sum(c-f) and sum((f-c)^2), writes new = c - 0.05*sum(c-f)
// exactly once, self-cleans the head, and the LAST block finalizes the loss.
__global__ void __launch_bounds__(THREADS_RK)
row_kernel(const float* __restrict__ features,
           const float* __restrict__ center_var,
           float*       __restrict__ out_centers,
           float*       __restrict__ out_loss) {
    const int t    = threadIdx.x;
    const int sub  = t >> 6;        // 0..3: row within block
    const int lane = t & 63;        // 0..63
    const long long row = (long long)blockIdx.x * ROWS_PER_BLOCK + sub;

    const float4* c4 = (const float4*)(center_var + row * EMBED_DIM);
    float4 c0 = __ldcs(c4 + lane);        // floats [0,256)
    float4 c1 = __ldcs(c4 + lane + 64);   // floats [256,512)

    float4 d0 = make_float4(0.f, 0.f, 0.f, 0.f);
    float4 d1 = make_float4(0.f, 0.f, 0.f, 0.f);
    float sq = 0.f;
    int   n  = 0;

    const int head = g_head[row];
    for (int h = head; h != 0; ) {
        const int s = h - 1;
        h = g_next[s];
        const float4* f4 = (const float4*)(features + (long long)s * EMBED_DIM);
        float4 f0 = __ldcs(f4 + lane);
        float4 f1 = __ldcs(f4 + lane + 64);
        float e;
        e = c0.x - f0.x; d0.x += e; sq += e * e;
        e = c0.y - f0.y; d0.y += e; sq += e * e;
        e = c0.z - f0.z; d0.z += e; sq += e * e;
        e = c0.w - f0.w; d0.w += e; sq += e * e;
        e = c1.x - f1.x; d1.x += e; sq += e * e;
        e = c1.y - f1.y; d1.y += e; sq += e * e;
        e = c1.z - f1.z; d1.z += e; sq += e * e;
        e = c1.w - f1.w; d1.w += e; sq += e * e;
        n++;
    }

    // Self-clean this row's list head for the next graph replay.
    if (lane == 0 && head != 0) g_head[row] = 0;

    // Output rows are +1 float misaligned (loss at out[0]) -> scalar stores.
    float* o0 = out_centers + row * EMBED_DIM + lane * 4;
    float* o1 = o0 + 256;
    __stcs(o0 + 0, c0.x - ONE_MINUS_ALPHA * d0.x);
    __stcs(o0 + 1, c0.y - ONE_MINUS_ALPHA * d0.y);
    __stcs(o0 + 2, c0.z - ONE_MINUS_ALPHA * d0.z);
    __stcs(o0 + 3, c0.w - ONE_MINUS_ALPHA * d0.w);
    __stcs(o1 + 0, c1.x - ONE_MINUS_ALPHA * d1.x);
    __stcs(o1 + 1, c1.y - ONE_MINUS_ALPHA * d1.y);
    __stcs(o1 + 2, c1.z - ONE_MINUS_ALPHA * d1.z);
    __stcs(o1 + 3, c1.w - ONE_MINUS_ALPHA * d1.w);

    // Block loss reduce (8 warps), one atomic per block that had samples.
    #pragma unroll
    for (int off = 16; off > 0; off >>= 1)
        sq += __shfl_down_sync(0xFFFFFFFFu, sq, off);
    __shared__ float ws[THREADS_RK / 32];
    if ((t & 31) == 0) ws[t >> 5] = sq;
    const int any = __syncthreads_or(n > 0);
    if (t == 0) {
        if (any) {
            float s = 0.f;
            #pragma unroll
            for (int i = 0; i < THREADS_RK / 32; i++) s += ws[i];
            atomicAdd(&g_loss_acc, (double)s);
        }
        // Last-block-done: finalize loss, reset scratch for the next replay.
        __threadfence();
        unsigned int prev = atomicAdd(&g_done, 1u);
        if (prev == (unsigned int)(gridDim.x - 1)) {
            *out_loss = (float)(g_loss_acc / ((double)BATCH * (double)EMBED_DIM));
            g_loss_acc = 0.0;
            g_done = 0u;
        }
    }
}

extern "C" void kernel_launch(void* const* d_in, const int* in_sizes, int n_in,
                              void* d_out, int out_size) {
    const float* features   = nullptr;
    const void*  labels_raw = nullptr;
    const float* center_var = nullptr;
    for (int i = 0; i < n_in; i++) {
        if (in_sizes[i] == BATCH)                        labels_raw = d_in[i];
        else if (in_sizes[i] == BATCH * EMBED_DIM)       features   = (const float*)d_in[i];
        else if (in_sizes[i] == NUM_CLASSES * EMBED_DIM) center_var = (const float*)d_in[i];
    }
    if (!features)   features   = (const float*)d_in[0];
    if (!labels_raw) labels_raw = d_in[1];
    if (!center_var) center_var = (const float*)d_in[2];

    float* out = (float*)d_out;
    long long centers_off = (long long)out_size - (long long)NUM_CLASSES * EMBED_DIM;
    if (centers_off < 0) centers_off = 0;
    float* out_loss    = out;
    float* out_centers = out + centers_off;

    build_kernel<<<64, 256>>>(labels_raw);
    row_kernel<<<GRID_RK, THREADS_RK>>>(features, center_var, out_centers, out_loss);
}